// round 1
// baseline (speedup 1.0000x reference)
#include <cuda_runtime.h>
#include <cuda_bf16.h>
#include <math.h>

// Problem constants
#define BATCH 2
#define SEQ   2048
#define DMODEL 1024
#define NHEADS 16
#define HDIM  64
#define MTOT  (BATCH * SEQ)            // 4096

// -------- scratch (no allocations allowed -> __device__ globals) --------
__device__ float g_Q[MTOT * DMODEL];
__device__ float g_K[MTOT * DMODEL];
__device__ float g_V[MTOT * DMODEL];
__device__ float g_Ctx[MTOT * DMODEL];

// ============================================================
// SGEMM (NT): C[M,N] = A[M,K] * B[N,K]^T  (+ optional bias[N])
// BM=128, BN=128, BK=16, 256 threads, 8x8 per thread.
// ============================================================
__global__ __launch_bounds__(256)
void sgemm_nt_kernel(const float* __restrict__ A,
                     const float* __restrict__ Bm,
                     const float* __restrict__ bias,
                     float* __restrict__ C,
                     int M, int N, int K)
{
    __shared__ float As[16][132];   // [k][m], pad 4 keeps 16B alignment
    __shared__ float Bs[16][132];   // [k][n]

    const int tid = threadIdx.x;
    const int tx = tid & 15;        // 0..15 -> N sub
    const int ty = tid >> 4;        // 0..15 -> M sub
    const int rowBase = blockIdx.y * 128;
    const int colBase = blockIdx.x * 128;

    const int lr  = tid >> 2;       // 0..63
    const int lc4 = tid & 3;        // 0..3 (float4 index in 16-wide K slab)

    const float* Aptr = A + (size_t)(rowBase + lr) * K + lc4 * 4;
    const float* Bptr = Bm + (size_t)(colBase + lr) * K + lc4 * 4;

    float acc[8][8];
    #pragma unroll
    for (int i = 0; i < 8; i++)
        #pragma unroll
        for (int j = 0; j < 8; j++) acc[i][j] = 0.0f;

    for (int k0 = 0; k0 < K; k0 += 16) {
        float4 a0 = *(const float4*)(Aptr + k0);
        float4 a1 = *(const float4*)(Aptr + (size_t)64 * K + k0);
        float4 b0 = *(const float4*)(Bptr + k0);
        float4 b1 = *(const float4*)(Bptr + (size_t)64 * K + k0);

        As[lc4*4+0][lr]    = a0.x; As[lc4*4+1][lr]    = a0.y;
        As[lc4*4+2][lr]    = a0.z; As[lc4*4+3][lr]    = a0.w;
        As[lc4*4+0][lr+64] = a1.x; As[lc4*4+1][lr+64] = a1.y;
        As[lc4*4+2][lr+64] = a1.z; As[lc4*4+3][lr+64] = a1.w;

        Bs[lc4*4+0][lr]    = b0.x; Bs[lc4*4+1][lr]    = b0.y;
        Bs[lc4*4+2][lr]    = b0.z; Bs[lc4*4+3][lr]    = b0.w;
        Bs[lc4*4+0][lr+64] = b1.x; Bs[lc4*4+1][lr+64] = b1.y;
        Bs[lc4*4+2][lr+64] = b1.z; Bs[lc4*4+3][lr+64] = b1.w;

        __syncthreads();

        #pragma unroll
        for (int k = 0; k < 16; k++) {
            float ra[8], rb[8];
            #pragma unroll
            for (int i = 0; i < 8; i++) ra[i] = As[k][ty*8 + i];
            #pragma unroll
            for (int j = 0; j < 8; j++) rb[j] = Bs[k][tx*8 + j];
            #pragma unroll
            for (int i = 0; i < 8; i++)
                #pragma unroll
                for (int j = 0; j < 8; j++)
                    acc[i][j] = fmaf(ra[i], rb[j], acc[i][j]);
        }
        __syncthreads();
    }

    #pragma unroll
    for (int i = 0; i < 8; i++) {
        const int r = rowBase + ty*8 + i;
        #pragma unroll
        for (int j = 0; j < 8; j++) {
            const int c = colBase + tx*8 + j;
            float v = acc[i][j];
            if (bias) v += bias[c];
            C[(size_t)r * N + c] = v;
        }
    }
}

// ============================================================
// Flash attention (causal), one CTA per (q-tile of 64, head, batch)
// 256 threads as 16x16; thread computes 4x4 of the 64x64 tiles.
// Smem (dynamic): Qs^T, Ks^T, Vs, Ps^T each [64][65] floats.
// ============================================================
#define FA_PAD 65
#define FA_TILE_FLOATS (64 * FA_PAD)
#define FA_SMEM_BYTES (4 * FA_TILE_FLOATS * (int)sizeof(float))

__global__ __launch_bounds__(256)
void flash_kernel(const float* __restrict__ Q,
                  const float* __restrict__ K,
                  const float* __restrict__ V,
                  float* __restrict__ Ctx)
{
    extern __shared__ float sm[];
    float* Qs = sm;                        // [d][r]
    float* Ks = sm + FA_TILE_FLOATS;       // [d][c]
    float* Vs = sm + 2 * FA_TILE_FLOATS;   // [c][d]
    float* Ps = sm + 3 * FA_TILE_FLOATS;   // [c][r]

    const int tid = threadIdx.x;
    const int tx = tid & 15;   // column group
    const int ty = tid >> 4;   // row group
    const int qt = blockIdx.x;
    const int h  = blockIdx.y;
    const int b  = blockIdx.z;

    const size_t headOff = (size_t)b * SEQ * DMODEL + (size_t)h * HDIM;
    const int q0 = qt * 64;

    // load Q tile, transposed into Qs[d][r]
    #pragma unroll
    for (int it = 0; it < 4; it++) {
        int f  = tid + it * 256;           // 0..1023
        int r  = f >> 4;
        int c4 = (f & 15) * 4;
        float4 v = *(const float4*)(Q + headOff + (size_t)(q0 + r) * DMODEL + c4);
        Qs[(c4+0)*FA_PAD + r] = v.x;
        Qs[(c4+1)*FA_PAD + r] = v.y;
        Qs[(c4+2)*FA_PAD + r] = v.z;
        Qs[(c4+3)*FA_PAD + r] = v.w;
    }

    float mrow[4], lrow[4], o[4][4];
    #pragma unroll
    for (int i = 0; i < 4; i++) {
        mrow[i] = -1e30f; lrow[i] = 0.0f;
        #pragma unroll
        for (int j = 0; j < 4; j++) o[i][j] = 0.0f;
    }
    __syncthreads();

    for (int jt = 0; jt <= qt; jt++) {
        const int k0 = jt * 64;
        // load K (transposed) and V tiles
        #pragma unroll
        for (int it = 0; it < 4; it++) {
            int f  = tid + it * 256;
            int r  = f >> 4;
            int c4 = (f & 15) * 4;
            float4 kv = *(const float4*)(K + headOff + (size_t)(k0 + r) * DMODEL + c4);
            Ks[(c4+0)*FA_PAD + r] = kv.x;
            Ks[(c4+1)*FA_PAD + r] = kv.y;
            Ks[(c4+2)*FA_PAD + r] = kv.z;
            Ks[(c4+3)*FA_PAD + r] = kv.w;
            float4 vv = *(const float4*)(V + headOff + (size_t)(k0 + r) * DMODEL + c4);
            Vs[r*FA_PAD + c4 + 0] = vv.x;
            Vs[r*FA_PAD + c4 + 1] = vv.y;
            Vs[r*FA_PAD + c4 + 2] = vv.z;
            Vs[r*FA_PAD + c4 + 3] = vv.w;
        }
        __syncthreads();

        // scores S = Q K^T * 0.125
        float s[4][4];
        #pragma unroll
        for (int i = 0; i < 4; i++)
            #pragma unroll
            for (int j = 0; j < 4; j++) s[i][j] = 0.0f;

        #pragma unroll 8
        for (int d = 0; d < 64; d++) {
            float qa[4], kb[4];
            #pragma unroll
            for (int i = 0; i < 4; i++) qa[i] = Qs[d*FA_PAD + ty*4 + i];
            #pragma unroll
            for (int j = 0; j < 4; j++) kb[j] = Ks[d*FA_PAD + tx*4 + j];
            #pragma unroll
            for (int i = 0; i < 4; i++)
                #pragma unroll
                for (int j = 0; j < 4; j++)
                    s[i][j] = fmaf(qa[i], kb[j], s[i][j]);
        }

        const bool diag = (jt == qt);
        #pragma unroll
        for (int i = 0; i < 4; i++)
            #pragma unroll
            for (int j = 0; j < 4; j++) {
                s[i][j] *= 0.125f;
                if (diag && (tx*4 + j) > (ty*4 + i)) s[i][j] = -1e30f;
            }

        // row max over this tile (reduce across the 16 tx lanes)
        float tmax[4];
        #pragma unroll
        for (int i = 0; i < 4; i++) {
            tmax[i] = fmaxf(fmaxf(s[i][0], s[i][1]), fmaxf(s[i][2], s[i][3]));
        }
        #pragma unroll
        for (int off = 8; off >= 1; off >>= 1) {
            #pragma unroll
            for (int i = 0; i < 4; i++)
                tmax[i] = fmaxf(tmax[i], __shfl_xor_sync(0xffffffffu, tmax[i], off));
        }

        float mnew[4], scl[4], rsum[4];
        #pragma unroll
        for (int i = 0; i < 4; i++) {
            mnew[i] = fmaxf(mrow[i], tmax[i]);
            scl[i]  = __expf(mrow[i] - mnew[i]);
            rsum[i] = 0.0f;
            #pragma unroll
            for (int j = 0; j < 4; j++) {
                s[i][j] = __expf(s[i][j] - mnew[i]);   // becomes P
                rsum[i] += s[i][j];
            }
        }
        #pragma unroll
        for (int off = 8; off >= 1; off >>= 1) {
            #pragma unroll
            for (int i = 0; i < 4; i++)
                rsum[i] += __shfl_xor_sync(0xffffffffu, rsum[i], off);
        }
        #pragma unroll
        for (int i = 0; i < 4; i++) {
            lrow[i] = lrow[i] * scl[i] + rsum[i];
            mrow[i] = mnew[i];
            #pragma unroll
            for (int j = 0; j < 4; j++) o[i][j] *= scl[i];
        }

        // stage P transposed: Ps[c][r]
        #pragma unroll
        for (int i = 0; i < 4; i++)
            #pragma unroll
            for (int j = 0; j < 4; j++)
                Ps[(tx*4 + j)*FA_PAD + ty*4 + i] = s[i][j];
        __syncthreads();

        // O += P V
        #pragma unroll 8
        for (int c = 0; c < 64; c++) {
            float pa[4], vb[4];
            #pragma unroll
            for (int i = 0; i < 4; i++) pa[i] = Ps[c*FA_PAD + ty*4 + i];
            #pragma unroll
            for (int j = 0; j < 4; j++) vb[j] = Vs[c*FA_PAD + tx*4 + j];
            #pragma unroll
            for (int i = 0; i < 4; i++)
                #pragma unroll
                for (int j = 0; j < 4; j++)
                    o[i][j] = fmaf(pa[i], vb[j], o[i][j]);
        }
        __syncthreads();
    }

    // normalize + write ctx
    #pragma unroll
    for (int i = 0; i < 4; i++) {
        const float inv = 1.0f / lrow[i];
        const int r = q0 + ty*4 + i;
        #pragma unroll
        for (int j = 0; j < 4; j++)
            Ctx[headOff + (size_t)r * DMODEL + tx*4 + j] = o[i][j] * inv;
    }
}

// ============================================================
extern "C" void kernel_launch(void* const* d_in, const int* in_sizes, int n_in,
                              void* d_out, int out_size)
{
    const float* x  = (const float*)d_in[0];
    const float* Wq = (const float*)d_in[1];
    const float* Wk = (const float*)d_in[2];
    const float* Wv = (const float*)d_in[3];
    const float* Wo = (const float*)d_in[4];
    const float* bo = (const float*)d_in[5];
    float* out = (float*)d_out;

    float *Qb, *Kb, *Vb, *Cb;
    cudaGetSymbolAddress((void**)&Qb, g_Q);
    cudaGetSymbolAddress((void**)&Kb, g_K);
    cudaGetSymbolAddress((void**)&Vb, g_V);
    cudaGetSymbolAddress((void**)&Cb, g_Ctx);

    cudaFuncSetAttribute(flash_kernel,
                         cudaFuncAttributeMaxDynamicSharedMemorySize,
                         FA_SMEM_BYTES);

    dim3 gGemm(DMODEL / 128, MTOT / 128);   // (8, 32)
    // QKV projections
    sgemm_nt_kernel<<<gGemm, 256>>>(x, Wq, nullptr, Qb, MTOT, DMODEL, DMODEL);
    sgemm_nt_kernel<<<gGemm, 256>>>(x, Wk, nullptr, Kb, MTOT, DMODEL, DMODEL);
    sgemm_nt_kernel<<<gGemm, 256>>>(x, Wv, nullptr, Vb, MTOT, DMODEL, DMODEL);

    // causal flash attention
    dim3 gFa(SEQ / 64, NHEADS, BATCH);      // (32, 16, 2)
    flash_kernel<<<gFa, 256, FA_SMEM_BYTES>>>(Qb, Kb, Vb, Cb);

    // output projection + bias
    sgemm_nt_kernel<<<gGemm, 256>>>(Cb, Wo, bo, out, MTOT, DMODEL, DMODEL);
}

// round 3
// speedup vs baseline: 1.8081x; 1.8081x over previous
#include <cuda_runtime.h>
#include <cuda_fp16.h>
#include <math.h>
#include <stdint.h>

// Problem constants
#define BATCH 2
#define SEQ   2048
#define DMODEL 1024
#define NHEADS 16
#define HDIM  64
#define MTOT  (BATCH * SEQ)            // 4096

// -------- scratch (no allocations allowed -> __device__ globals) --------
__device__ float g_Q[MTOT * DMODEL];
__device__ float g_K[MTOT * DMODEL];
__device__ float g_V[MTOT * DMODEL];
__device__ float g_Ctx[MTOT * DMODEL];

__device__ __half g_Xh  [(size_t)MTOT * DMODEL];
__device__ __half g_Ctxh[(size_t)MTOT * DMODEL];
__device__ __half g_Wqh [(size_t)DMODEL * DMODEL];
__device__ __half g_Wkh [(size_t)DMODEL * DMODEL];
__device__ __half g_Wvh [(size_t)DMODEL * DMODEL];
__device__ __half g_Woh [(size_t)DMODEL * DMODEL];

// ================= helpers =================
__device__ __forceinline__ uint32_t smem_u32(const void* p) {
    uint32_t a;
    asm("{ .reg .u64 t; cvta.to.shared.u64 t, %1; cvt.u32.u64 %0, t; }"
        : "=r"(a) : "l"(p));
    return a;
}

#define SWZ128(x) ((x) ^ (((x) >> 3) & 0x70))

#define CP_ASYNC16(dst, src) \
    asm volatile("cp.async.cg.shared.global [%0], [%1], 16;" \
                 :: "r"(dst), "l"(src) : "memory")
#define CP_ASYNC_COMMIT() asm volatile("cp.async.commit_group;" ::: "memory")

#define LDSM_X4(r, addr) \
    asm volatile("ldmatrix.sync.aligned.m8n8.x4.shared.b16 {%0,%1,%2,%3}, [%4];" \
        : "=r"((r)[0]), "=r"((r)[1]), "=r"((r)[2]), "=r"((r)[3]) : "r"(addr))

#define MMA16816(d, a, b0, b1) \
    asm volatile("mma.sync.aligned.m16n8k16.row.col.f32.f16.f16.f32 " \
        "{%0,%1,%2,%3}, {%4,%5,%6,%7}, {%8,%9}, {%0,%1,%2,%3};" \
        : "+f"((d)[0]), "+f"((d)[1]), "+f"((d)[2]), "+f"((d)[3]) \
        : "r"((a)[0]), "r"((a)[1]), "r"((a)[2]), "r"((a)[3]), "r"(b0), "r"(b1))

// ============================================================
// fp32 -> fp16 conversion (vectorized)
// ============================================================
__global__ void f2h_kernel(const float* __restrict__ src,
                           __half* __restrict__ dst, int n)
{
    int i = (blockIdx.x * blockDim.x + threadIdx.x) * 4;
    if (i >= n) return;
    float4 v = *(const float4*)(src + i);
    __half2 h0 = __floats2half2_rn(v.x, v.y);
    __half2 h1 = __floats2half2_rn(v.z, v.w);
    *(__half2*)(dst + i)     = h0;
    *(__half2*)(dst + i + 2) = h1;
}

// ============================================================
// fp16 HMMA GEMM (NT): C[M,N] = A[M,K] * B[N,K]^T (+bias, fp32 out)
// 128x128 CTA tile, BK=64, 8 warps (2m x 4n, warp tile 64x32),
// double-buffered cp.async, SW128 smem swizzle, ldmatrix fragments.
// ============================================================
#define HG_TILE  16384                 // 128 rows x 128B
#define HG_SMEM  (4 * HG_TILE)         // 64 KB (2 bufs x (A+B))
#define HG_BK    64                    // fp16 elems per chunk

__global__ __launch_bounds__(256)
void hgemm_nt(const __half* __restrict__ A,
              const __half* __restrict__ B,
              const float* __restrict__ bias,
              float* __restrict__ C,
              int M, int N, int K)
{
    extern __shared__ char sm[];
    const uint32_t smem_base = smem_u32(sm);
    const int tid  = threadIdx.x;
    const int lane = tid & 31;
    const int wid  = tid >> 5;
    const int m0 = blockIdx.y * 128;
    const int n0 = blockIdx.x * 128;
    const int warp_m = (wid >> 2) * 64;    // 0 or 64
    const int warp_n = (wid & 3) * 32;     // 0,32,64,96

    float d[4][4][4];
    #pragma unroll
    for (int mt = 0; mt < 4; mt++)
        #pragma unroll
        for (int nt = 0; nt < 4; nt++)
            #pragma unroll
            for (int r = 0; r < 4; r++) d[mt][nt][r] = 0.0f;

    const int nchunks = K / HG_BK;

    // --- chunk loader: 8 cp.async x 16B per thread (A:4, B:4) ---
    auto load_chunk = [&](int c, int buf) {
        const uint32_t aBase = smem_base + buf * (2 * HG_TILE);
        const uint32_t bBase = aBase + HG_TILE;
        const char* Ag = (const char*)(A + (size_t)m0 * K + c * HG_BK);
        const char* Bg = (const char*)(B + (size_t)n0 * K + c * HG_BK);
        #pragma unroll
        for (int t = 0; t < 4; t++) {
            int g   = tid + t * 256;      // 0..1023
            int row = g >> 3;
            int seg = g & 7;
            uint32_t sw = SWZ128((uint32_t)(row * 128 + seg * 16));
            CP_ASYNC16(aBase + sw, Ag + (size_t)row * K * 2 + seg * 16);
            CP_ASYNC16(bBase + sw, Bg + (size_t)row * K * 2 + seg * 16);
        }
        CP_ASYNC_COMMIT();
    };

    load_chunk(0, 0);

    for (int c = 0; c < nchunks; c++) {
        const int buf = c & 1;
        if (c + 1 < nchunks) {
            load_chunk(c + 1, (c + 1) & 1);
            asm volatile("cp.async.wait_group 1;" ::: "memory");
        } else {
            asm volatile("cp.async.wait_group 0;" ::: "memory");
        }
        __syncthreads();

        const uint32_t aBase = smem_base + buf * (2 * HG_TILE);
        const uint32_t bBase = aBase + HG_TILE;

        #pragma unroll
        for (int ks = 0; ks < 4; ks++) {
            uint32_t a[4][4], b[2][4];
            const int kbyte = ks * 32 + ((lane >> 4) << 4);
            #pragma unroll
            for (int mt = 0; mt < 4; mt++) {
                const int row = warp_m + mt * 16 + (lane & 15);
                LDSM_X4(a[mt], aBase + SWZ128((uint32_t)(row * 128 + kbyte)));
            }
            #pragma unroll
            for (int nt2 = 0; nt2 < 2; nt2++) {
                const int row = warp_n + nt2 * 16 + (lane & 15);
                LDSM_X4(b[nt2], bBase + SWZ128((uint32_t)(row * 128 + kbyte)));
            }
            #pragma unroll
            for (int mt = 0; mt < 4; mt++)
                #pragma unroll
                for (int nt = 0; nt < 4; nt++) {
                    const uint32_t b0 = b[nt >> 1][(nt & 1) ? 1 : 0];
                    const uint32_t b1 = b[nt >> 1][(nt & 1) ? 3 : 2];
                    MMA16816(d[mt][nt], a[mt], b0, b1);
                }
        }
        __syncthreads();
    }

    // --- epilogue: fp32 out (+bias) ---
    #pragma unroll
    for (int mt = 0; mt < 4; mt++) {
        const int row = m0 + warp_m + mt * 16 + (lane >> 2);
        #pragma unroll
        for (int nt = 0; nt < 4; nt++) {
            const int col = n0 + warp_n + nt * 8 + (lane & 3) * 2;
            float bx = 0.0f, by = 0.0f;
            if (bias) { bx = bias[col]; by = bias[col + 1]; }
            float2 v0 = { d[mt][nt][0] + bx, d[mt][nt][1] + by };
            float2 v1 = { d[mt][nt][2] + bx, d[mt][nt][3] + by };
            *(float2*)(C + (size_t)row * N + col)       = v0;
            *(float2*)(C + (size_t)(row + 8) * N + col) = v1;
        }
    }
}

// ============================================================
// Flash attention (causal) — fp32 SIMT (unchanged, passing)
// ============================================================
#define FA_PAD 65
#define FA_TILE_FLOATS (64 * FA_PAD)
#define FA_SMEM_BYTES (4 * FA_TILE_FLOATS * (int)sizeof(float))

__global__ __launch_bounds__(256)
void flash_kernel(const float* __restrict__ Q,
                  const float* __restrict__ K,
                  const float* __restrict__ V,
                  float* __restrict__ Ctx)
{
    extern __shared__ float smf[];
    float* Qs = smf;
    float* Ks = smf + FA_TILE_FLOATS;
    float* Vs = smf + 2 * FA_TILE_FLOATS;
    float* Ps = smf + 3 * FA_TILE_FLOATS;

    const int tid = threadIdx.x;
    const int tx = tid & 15;
    const int ty = tid >> 4;
    const int qt = blockIdx.x;
    const int h  = blockIdx.y;
    const int b  = blockIdx.z;

    const size_t headOff = (size_t)b * SEQ * DMODEL + (size_t)h * HDIM;
    const int q0 = qt * 64;

    #pragma unroll
    for (int it = 0; it < 4; it++) {
        int f  = tid + it * 256;
        int r  = f >> 4;
        int c4 = (f & 15) * 4;
        float4 v = *(const float4*)(Q + headOff + (size_t)(q0 + r) * DMODEL + c4);
        Qs[(c4+0)*FA_PAD + r] = v.x;
        Qs[(c4+1)*FA_PAD + r] = v.y;
        Qs[(c4+2)*FA_PAD + r] = v.z;
        Qs[(c4+3)*FA_PAD + r] = v.w;
    }

    float mrow[4], lrow[4], o[4][4];
    #pragma unroll
    for (int i = 0; i < 4; i++) {
        mrow[i] = -1e30f; lrow[i] = 0.0f;
        #pragma unroll
        for (int j = 0; j < 4; j++) o[i][j] = 0.0f;
    }
    __syncthreads();

    for (int jt = 0; jt <= qt; jt++) {
        const int k0 = jt * 64;
        #pragma unroll
        for (int it = 0; it < 4; it++) {
            int f  = tid + it * 256;
            int r  = f >> 4;
            int c4 = (f & 15) * 4;
            float4 kv = *(const float4*)(K + headOff + (size_t)(k0 + r) * DMODEL + c4);
            Ks[(c4+0)*FA_PAD + r] = kv.x;
            Ks[(c4+1)*FA_PAD + r] = kv.y;
            Ks[(c4+2)*FA_PAD + r] = kv.z;
            Ks[(c4+3)*FA_PAD + r] = kv.w;
            float4 vv = *(const float4*)(V + headOff + (size_t)(k0 + r) * DMODEL + c4);
            Vs[r*FA_PAD + c4 + 0] = vv.x;
            Vs[r*FA_PAD + c4 + 1] = vv.y;
            Vs[r*FA_PAD + c4 + 2] = vv.z;
            Vs[r*FA_PAD + c4 + 3] = vv.w;
        }
        __syncthreads();

        float s[4][4];
        #pragma unroll
        for (int i = 0; i < 4; i++)
            #pragma unroll
            for (int j = 0; j < 4; j++) s[i][j] = 0.0f;

        #pragma unroll 8
        for (int dd = 0; dd < 64; dd++) {
            float qa[4], kb[4];
            #pragma unroll
            for (int i = 0; i < 4; i++) qa[i] = Qs[dd*FA_PAD + ty*4 + i];
            #pragma unroll
            for (int j = 0; j < 4; j++) kb[j] = Ks[dd*FA_PAD + tx*4 + j];
            #pragma unroll
            for (int i = 0; i < 4; i++)
                #pragma unroll
                for (int j = 0; j < 4; j++)
                    s[i][j] = fmaf(qa[i], kb[j], s[i][j]);
        }

        const bool diag = (jt == qt);
        #pragma unroll
        for (int i = 0; i < 4; i++)
            #pragma unroll
            for (int j = 0; j < 4; j++) {
                s[i][j] *= 0.125f;
                if (diag && (tx*4 + j) > (ty*4 + i)) s[i][j] = -1e30f;
            }

        float tmax[4];
        #pragma unroll
        for (int i = 0; i < 4; i++)
            tmax[i] = fmaxf(fmaxf(s[i][0], s[i][1]), fmaxf(s[i][2], s[i][3]));
        #pragma unroll
        for (int off = 8; off >= 1; off >>= 1) {
            #pragma unroll
            for (int i = 0; i < 4; i++)
                tmax[i] = fmaxf(tmax[i], __shfl_xor_sync(0xffffffffu, tmax[i], off));
        }

        float mnew[4], scl[4], rsum[4];
        #pragma unroll
        for (int i = 0; i < 4; i++) {
            mnew[i] = fmaxf(mrow[i], tmax[i]);
            scl[i]  = __expf(mrow[i] - mnew[i]);
            rsum[i] = 0.0f;
            #pragma unroll
            for (int j = 0; j < 4; j++) {
                s[i][j] = __expf(s[i][j] - mnew[i]);
                rsum[i] += s[i][j];
            }
        }
        #pragma unroll
        for (int off = 8; off >= 1; off >>= 1) {
            #pragma unroll
            for (int i = 0; i < 4; i++)
                rsum[i] += __shfl_xor_sync(0xffffffffu, rsum[i], off);
        }
        #pragma unroll
        for (int i = 0; i < 4; i++) {
            lrow[i] = lrow[i] * scl[i] + rsum[i];
            mrow[i] = mnew[i];
            #pragma unroll
            for (int j = 0; j < 4; j++) o[i][j] *= scl[i];
        }

        #pragma unroll
        for (int i = 0; i < 4; i++)
            #pragma unroll
            for (int j = 0; j < 4; j++)
                Ps[(tx*4 + j)*FA_PAD + ty*4 + i] = s[i][j];
        __syncthreads();

        #pragma unroll 8
        for (int c = 0; c < 64; c++) {
            float pa[4], vb[4];
            #pragma unroll
            for (int i = 0; i < 4; i++) pa[i] = Ps[c*FA_PAD + ty*4 + i];
            #pragma unroll
            for (int j = 0; j < 4; j++) vb[j] = Vs[c*FA_PAD + tx*4 + j];
            #pragma unroll
            for (int i = 0; i < 4; i++)
                #pragma unroll
                for (int j = 0; j < 4; j++)
                    o[i][j] = fmaf(pa[i], vb[j], o[i][j]);
        }
        __syncthreads();
    }

    #pragma unroll
    for (int i = 0; i < 4; i++) {
        const float inv = 1.0f / lrow[i];
        const int r = q0 + ty*4 + i;
        #pragma unroll
        for (int j = 0; j < 4; j++)
            Ctx[headOff + (size_t)r * DMODEL + tx*4 + j] = o[i][j] * inv;
    }
}

// ============================================================
extern "C" void kernel_launch(void* const* d_in, const int* in_sizes, int n_in,
                              void* d_out, int out_size)
{
    const float* x  = (const float*)d_in[0];
    const float* Wq = (const float*)d_in[1];
    const float* Wk = (const float*)d_in[2];
    const float* Wv = (const float*)d_in[3];
    const float* Wo = (const float*)d_in[4];
    const float* bo = (const float*)d_in[5];
    float* out = (float*)d_out;

    float *Qb, *Kb, *Vb, *Cb;
    __half *Xh, *Ch, *Wqh, *Wkh, *Wvh, *Woh;
    cudaGetSymbolAddress((void**)&Qb, g_Q);
    cudaGetSymbolAddress((void**)&Kb, g_K);
    cudaGetSymbolAddress((void**)&Vb, g_V);
    cudaGetSymbolAddress((void**)&Cb, g_Ctx);
    cudaGetSymbolAddress((void**)&Xh, g_Xh);
    cudaGetSymbolAddress((void**)&Ch, g_Ctxh);
    cudaGetSymbolAddress((void**)&Wqh, g_Wqh);
    cudaGetSymbolAddress((void**)&Wkh, g_Wkh);
    cudaGetSymbolAddress((void**)&Wvh, g_Wvh);
    cudaGetSymbolAddress((void**)&Woh, g_Woh);

    cudaFuncSetAttribute(flash_kernel,
                         cudaFuncAttributeMaxDynamicSharedMemorySize, FA_SMEM_BYTES);
    cudaFuncSetAttribute(hgemm_nt,
                         cudaFuncAttributeMaxDynamicSharedMemorySize, HG_SMEM);

    // fp32 -> fp16 conversions
    const int nX = MTOT * DMODEL, nW = DMODEL * DMODEL;
    f2h_kernel<<<nX / 4 / 256, 256>>>(x,  Xh,  nX);
    f2h_kernel<<<nW / 4 / 256, 256>>>(Wq, Wqh, nW);
    f2h_kernel<<<nW / 4 / 256, 256>>>(Wk, Wkh, nW);
    f2h_kernel<<<nW / 4 / 256, 256>>>(Wv, Wvh, nW);
    f2h_kernel<<<nW / 4 / 256, 256>>>(Wo, Woh, nW);

    dim3 gGemm(DMODEL / 128, MTOT / 128);   // (8, 32)
    hgemm_nt<<<gGemm, 256, HG_SMEM>>>(Xh, Wqh, nullptr, Qb, MTOT, DMODEL, DMODEL);
    hgemm_nt<<<gGemm, 256, HG_SMEM>>>(Xh, Wkh, nullptr, Kb, MTOT, DMODEL, DMODEL);
    hgemm_nt<<<gGemm, 256, HG_SMEM>>>(Xh, Wvh, nullptr, Vb, MTOT, DMODEL, DMODEL);

    dim3 gFa(SEQ / 64, NHEADS, BATCH);      // (32, 16, 2)
    flash_kernel<<<gFa, 256, FA_SMEM_BYTES>>>(Qb, Kb, Vb, Cb);

    f2h_kernel<<<nX / 4 / 256, 256>>>(Cb, Ch, nX);
    hgemm_nt<<<gGemm, 256, HG_SMEM>>>(Ch, Woh, bo, out, MTOT, DMODEL, DMODEL);
}

// round 4
// speedup vs baseline: 6.7490x; 3.7327x over previous
#include <cuda_runtime.h>
#include <cuda_fp16.h>
#include <math.h>
#include <stdint.h>

// Problem constants
#define BATCH 2
#define SEQ   2048
#define DMODEL 1024
#define NHEADS 16
#define HDIM  64
#define MTOT  (BATCH * SEQ)            // 4096

// -------- scratch (no allocations allowed -> __device__ globals) --------
__device__ __half g_Qh  [(size_t)MTOT * DMODEL];
__device__ __half g_Kh  [(size_t)MTOT * DMODEL];
__device__ __half g_Vh  [(size_t)MTOT * DMODEL];
__device__ __half g_Ctxh[(size_t)MTOT * DMODEL];
__device__ __half g_Xh  [(size_t)MTOT * DMODEL];
__device__ __half g_Wqh [(size_t)DMODEL * DMODEL];
__device__ __half g_Wkh [(size_t)DMODEL * DMODEL];
__device__ __half g_Wvh [(size_t)DMODEL * DMODEL];
__device__ __half g_Woh [(size_t)DMODEL * DMODEL];

// ================= helpers =================
__device__ __forceinline__ uint32_t smem_u32(const void* p) {
    uint32_t a;
    asm("{ .reg .u64 t; cvta.to.shared.u64 t, %1; cvt.u32.u64 %0, t; }"
        : "=r"(a) : "l"(p));
    return a;
}

#define SWZ128(x) ((x) ^ (((x) >> 3) & 0x70))

#define CP_ASYNC16(dst, src) \
    asm volatile("cp.async.cg.shared.global [%0], [%1], 16;" \
                 :: "r"(dst), "l"(src) : "memory")
#define CP_ASYNC_COMMIT() asm volatile("cp.async.commit_group;" ::: "memory")

#define LDSM_X4(r, addr) \
    asm volatile("ldmatrix.sync.aligned.m8n8.x4.shared.b16 {%0,%1,%2,%3}, [%4];" \
        : "=r"((r)[0]), "=r"((r)[1]), "=r"((r)[2]), "=r"((r)[3]) : "r"(addr))

#define LDSM_X4_T(r, addr) \
    asm volatile("ldmatrix.sync.aligned.m8n8.x4.trans.shared.b16 {%0,%1,%2,%3}, [%4];" \
        : "=r"((r)[0]), "=r"((r)[1]), "=r"((r)[2]), "=r"((r)[3]) : "r"(addr))

#define MMA16816(d, a, b0, b1) \
    asm volatile("mma.sync.aligned.m16n8k16.row.col.f32.f16.f16.f32 " \
        "{%0,%1,%2,%3}, {%4,%5,%6,%7}, {%8,%9}, {%0,%1,%2,%3};" \
        : "+f"((d)[0]), "+f"((d)[1]), "+f"((d)[2]), "+f"((d)[3]) \
        : "r"((a)[0]), "r"((a)[1]), "r"((a)[2]), "r"((a)[3]), "r"(b0), "r"(b1))

__device__ __forceinline__ uint32_t packh2(float a, float b) {
    __half2 h = __floats2half2_rn(a, b);
    return *reinterpret_cast<uint32_t*>(&h);
}

// ============================================================
// fp32 -> fp16 conversion (vectorized)
// ============================================================
__global__ void f2h_kernel(const float* __restrict__ src,
                           __half* __restrict__ dst, int n)
{
    int i = (blockIdx.x * blockDim.x + threadIdx.x) * 4;
    if (i >= n) return;
    float4 v = *(const float4*)(src + i);
    *(__half2*)(dst + i)     = __floats2half2_rn(v.x, v.y);
    *(__half2*)(dst + i + 2) = __floats2half2_rn(v.z, v.w);
}

// ============================================================
// fp16 HMMA GEMM (NT): C[M,N] = A[M,K] * B[N,K]^T (+bias)
// 128x128 CTA tile, BK=64, 8 warps (2m x 4n), double-buffered cp.async.
// Output type templated (half for intermediates, float for final).
// ============================================================
#define HG_TILE  16384                 // 128 rows x 128B
#define HG_SMEM  (4 * HG_TILE)         // 64 KB

template <typename OT>
__global__ __launch_bounds__(256)
void hgemm_nt(const __half* __restrict__ A,
              const __half* __restrict__ B,
              const float* __restrict__ bias,
              OT* __restrict__ C,
              int M, int N, int K)
{
    extern __shared__ char sm[];
    const uint32_t smem_base = smem_u32(sm);
    const int tid  = threadIdx.x;
    const int lane = tid & 31;
    const int wid  = tid >> 5;
    const int m0 = blockIdx.y * 128;
    const int n0 = blockIdx.x * 128;
    const int warp_m = (wid >> 2) * 64;
    const int warp_n = (wid & 3) * 32;

    float d[4][4][4];
    #pragma unroll
    for (int mt = 0; mt < 4; mt++)
        #pragma unroll
        for (int nt = 0; nt < 4; nt++)
            #pragma unroll
            for (int r = 0; r < 4; r++) d[mt][nt][r] = 0.0f;

    const int nchunks = K / 64;

    auto load_chunk = [&](int c, int buf) {
        const uint32_t aBase = smem_base + buf * (2 * HG_TILE);
        const uint32_t bBase = aBase + HG_TILE;
        const char* Ag = (const char*)(A + (size_t)m0 * K + c * 64);
        const char* Bg = (const char*)(B + (size_t)n0 * K + c * 64);
        #pragma unroll
        for (int t = 0; t < 4; t++) {
            int g   = tid + t * 256;
            int row = g >> 3;
            int seg = g & 7;
            uint32_t sw = SWZ128((uint32_t)(row * 128 + seg * 16));
            CP_ASYNC16(aBase + sw, Ag + (size_t)row * K * 2 + seg * 16);
            CP_ASYNC16(bBase + sw, Bg + (size_t)row * K * 2 + seg * 16);
        }
        CP_ASYNC_COMMIT();
    };

    load_chunk(0, 0);

    for (int c = 0; c < nchunks; c++) {
        const int buf = c & 1;
        if (c + 1 < nchunks) {
            load_chunk(c + 1, (c + 1) & 1);
            asm volatile("cp.async.wait_group 1;" ::: "memory");
        } else {
            asm volatile("cp.async.wait_group 0;" ::: "memory");
        }
        __syncthreads();

        const uint32_t aBase = smem_base + buf * (2 * HG_TILE);
        const uint32_t bBase = aBase + HG_TILE;

        #pragma unroll
        for (int ks = 0; ks < 4; ks++) {
            uint32_t a[4][4], b[2][4];
            const int kbyte = ks * 32 + ((lane >> 4) << 4);
            #pragma unroll
            for (int mt = 0; mt < 4; mt++) {
                const int row = warp_m + mt * 16 + (lane & 15);
                LDSM_X4(a[mt], aBase + SWZ128((uint32_t)(row * 128 + kbyte)));
            }
            #pragma unroll
            for (int nt2 = 0; nt2 < 2; nt2++) {
                const int row = warp_n + nt2 * 16 + (lane & 15);
                LDSM_X4(b[nt2], bBase + SWZ128((uint32_t)(row * 128 + kbyte)));
            }
            #pragma unroll
            for (int mt = 0; mt < 4; mt++)
                #pragma unroll
                for (int nt = 0; nt < 4; nt++) {
                    const uint32_t b0 = b[nt >> 1][(nt & 1) ? 1 : 0];
                    const uint32_t b1 = b[nt >> 1][(nt & 1) ? 3 : 2];
                    MMA16816(d[mt][nt], a[mt], b0, b1);
                }
        }
        __syncthreads();
    }

    #pragma unroll
    for (int mt = 0; mt < 4; mt++) {
        const int row = m0 + warp_m + mt * 16 + (lane >> 2);
        #pragma unroll
        for (int nt = 0; nt < 4; nt++) {
            const int col = n0 + warp_n + nt * 8 + (lane & 3) * 2;
            float bx = 0.0f, by = 0.0f;
            if (bias) { bx = bias[col]; by = bias[col + 1]; }
            float v00 = d[mt][nt][0] + bx, v01 = d[mt][nt][1] + by;
            float v10 = d[mt][nt][2] + bx, v11 = d[mt][nt][3] + by;
            if constexpr (sizeof(OT) == 2) {
                *(__half2*)((__half*)C + (size_t)row * N + col) =
                    __floats2half2_rn(v00, v01);
                *(__half2*)((__half*)C + (size_t)(row + 8) * N + col) =
                    __floats2half2_rn(v10, v11);
            } else {
                float2 a0 = { v00, v01 }, a1 = { v10, v11 };
                *(float2*)((float*)C + (size_t)row * N + col)       = a0;
                *(float2*)((float*)C + (size_t)(row + 8) * N + col) = a1;
            }
        }
    }
}

// ============================================================
// fp16 HMMA flash attention (causal)
// CTA: 128 q-rows x one head, 8 warps (each m16 x full tile).
// Bc = 64 kv per tile, K/V double-buffered cp.async.
// ============================================================
#define FL_Q_OFF 0
#define FL_K_OFF 16384                 // two 8KB K buffers: 16384, 24576
#define FL_V_OFF 32768                 // two 8KB V buffers: 32768, 40960
#define FL_SMEM  49152
#define FL_ALPHA 0.1803368801111244f   // 0.125 * log2(e)

__global__ __launch_bounds__(256)
void flash_hmma(const __half* __restrict__ Q,
                const __half* __restrict__ K,
                const __half* __restrict__ V,
                __half* __restrict__ Ctx)
{
    extern __shared__ char sm[];
    const uint32_t smem_base = smem_u32(sm);
    const int tid  = threadIdx.x;
    const int lane = tid & 31;
    const int wid  = tid >> 5;
    const int warp_m = wid * 16;
    const int q0 = blockIdx.x * 128;
    const int h  = blockIdx.y;
    const int b  = blockIdx.z;

    const size_t baseOff = (size_t)b * SEQ * DMODEL + (size_t)h * HDIM;

    // ---- load Q tile (128 x 64 halves = 128B rows) + KV tile 0 ----
    {
        #pragma unroll
        for (int t = 0; t < 4; t++) {
            int g   = tid + t * 256;          // 0..1023
            int row = g >> 3;
            int seg = g & 7;
            uint32_t sw = SWZ128((uint32_t)(row * 128 + seg * 16));
            CP_ASYNC16(smem_base + FL_Q_OFF + sw,
                       (const char*)(Q + baseOff + (size_t)(q0 + row) * DMODEL + seg * 8));
        }
        #pragma unroll
        for (int t = 0; t < 2; t++) {
            int g   = tid + t * 256;          // 0..511
            int row = g >> 3;
            int seg = g & 7;
            uint32_t sw = SWZ128((uint32_t)(row * 128 + seg * 16));
            CP_ASYNC16(smem_base + FL_K_OFF + sw,
                       (const char*)(K + baseOff + (size_t)row * DMODEL + seg * 8));
            CP_ASYNC16(smem_base + FL_V_OFF + sw,
                       (const char*)(V + baseOff + (size_t)row * DMODEL + seg * 8));
        }
        CP_ASYNC_COMMIT();
    }
    asm volatile("cp.async.wait_group 0;" ::: "memory");
    __syncthreads();

    // ---- Q fragments (resident): 4 k16 steps ----
    uint32_t qa[4][4];
    #pragma unroll
    for (int ks = 0; ks < 4; ks++) {
        const int row   = warp_m + (lane & 15);
        const int kbyte = ks * 32 + ((lane >> 4) << 4);
        LDSM_X4(qa[ks], smem_base + FL_Q_OFF + SWZ128((uint32_t)(row * 128 + kbyte)));
    }

    // ---- online softmax state (2 rows per thread: g, g+8) ----
    float m1 = -1e30f, m2 = -1e30f, l1 = 0.0f, l2 = 0.0f;
    float o[8][4];
    #pragma unroll
    for (int t = 0; t < 8; t++)
        #pragma unroll
        for (int r = 0; r < 4; r++) o[t][r] = 0.0f;

    const int g = lane >> 2;
    const int r1 = q0 + warp_m + g;
    const int r2 = r1 + 8;
    const int cbase = (lane & 3) * 2;
    const int ntiles = (q0 + 128) / 64;

    for (int jt = 0; jt < ntiles; jt++) {
        const int buf = jt & 1;
        const int k0  = jt * 64;

        // prefetch next tile
        if (jt + 1 < ntiles) {
            const int nbuf = (jt + 1) & 1;
            const int nk0  = (jt + 1) * 64;
            #pragma unroll
            for (int t = 0; t < 2; t++) {
                int gg  = tid + t * 256;
                int row = gg >> 3;
                int seg = gg & 7;
                uint32_t sw = SWZ128((uint32_t)(row * 128 + seg * 16));
                CP_ASYNC16(smem_base + FL_K_OFF + nbuf * 8192 + sw,
                           (const char*)(K + baseOff + (size_t)(nk0 + row) * DMODEL + seg * 8));
                CP_ASYNC16(smem_base + FL_V_OFF + nbuf * 8192 + sw,
                           (const char*)(V + baseOff + (size_t)(nk0 + row) * DMODEL + seg * 8));
            }
            CP_ASYNC_COMMIT();
        }

        const uint32_t kBase = smem_base + FL_K_OFF + buf * 8192;
        const uint32_t vBase = smem_base + FL_V_OFF + buf * 8192;

        // ---- S = Q K^T (raw scores) ----
        float s[8][4];
        #pragma unroll
        for (int t = 0; t < 8; t++)
            #pragma unroll
            for (int r = 0; r < 4; r++) s[t][r] = 0.0f;

        #pragma unroll
        for (int ks = 0; ks < 4; ks++) {
            const int kbyte = ks * 32 + ((lane >> 4) << 4);
            #pragma unroll
            for (int nb = 0; nb < 4; nb++) {
                uint32_t kb[4];
                const int row = nb * 16 + (lane & 15);
                LDSM_X4(kb, kBase + SWZ128((uint32_t)(row * 128 + kbyte)));
                MMA16816(s[nb * 2],     qa[ks], kb[0], kb[2]);
                MMA16816(s[nb * 2 + 1], qa[ks], kb[1], kb[3]);
            }
        }

        // ---- causal mask (only on warps whose rows intersect tile) ----
        if (k0 + 63 > q0 + warp_m) {
            #pragma unroll
            for (int t = 0; t < 8; t++) {
                const int c0 = k0 + t * 8 + cbase;
                if (c0 > r1)     s[t][0] = -1e30f;
                if (c0 + 1 > r1) s[t][1] = -1e30f;
                if (c0 > r2)     s[t][2] = -1e30f;
                if (c0 + 1 > r2) s[t][3] = -1e30f;
            }
        }

        // ---- online softmax ----
        float mx1 = -1e30f, mx2 = -1e30f;
        #pragma unroll
        for (int t = 0; t < 8; t++) {
            mx1 = fmaxf(mx1, fmaxf(s[t][0], s[t][1]));
            mx2 = fmaxf(mx2, fmaxf(s[t][2], s[t][3]));
        }
        mx1 = fmaxf(mx1, __shfl_xor_sync(0xffffffffu, mx1, 1));
        mx1 = fmaxf(mx1, __shfl_xor_sync(0xffffffffu, mx1, 2));
        mx2 = fmaxf(mx2, __shfl_xor_sync(0xffffffffu, mx2, 1));
        mx2 = fmaxf(mx2, __shfl_xor_sync(0xffffffffu, mx2, 2));

        const float mn1 = fmaxf(m1, mx1), mn2 = fmaxf(m2, mx2);
        const float sc1 = exp2f((m1 - mn1) * FL_ALPHA);
        const float sc2 = exp2f((m2 - mn2) * FL_ALPHA);
        float sum1 = 0.0f, sum2 = 0.0f;
        #pragma unroll
        for (int t = 0; t < 8; t++) {
            s[t][0] = exp2f((s[t][0] - mn1) * FL_ALPHA); sum1 += s[t][0];
            s[t][1] = exp2f((s[t][1] - mn1) * FL_ALPHA); sum1 += s[t][1];
            s[t][2] = exp2f((s[t][2] - mn2) * FL_ALPHA); sum2 += s[t][2];
            s[t][3] = exp2f((s[t][3] - mn2) * FL_ALPHA); sum2 += s[t][3];
        }
        sum1 += __shfl_xor_sync(0xffffffffu, sum1, 1);
        sum1 += __shfl_xor_sync(0xffffffffu, sum1, 2);
        sum2 += __shfl_xor_sync(0xffffffffu, sum2, 1);
        sum2 += __shfl_xor_sync(0xffffffffu, sum2, 2);

        l1 = l1 * sc1 + sum1;
        l2 = l2 * sc2 + sum2;
        m1 = mn1; m2 = mn2;

        #pragma unroll
        for (int t = 0; t < 8; t++) {
            o[t][0] *= sc1; o[t][1] *= sc1;
            o[t][2] *= sc2; o[t][3] *= sc2;
        }

        // ---- P fragments (register relayout, no smem) ----
        uint32_t pa[4][4];
        #pragma unroll
        for (int ks = 0; ks < 4; ks++) {
            pa[ks][0] = packh2(s[2 * ks][0],     s[2 * ks][1]);
            pa[ks][1] = packh2(s[2 * ks][2],     s[2 * ks][3]);
            pa[ks][2] = packh2(s[2 * ks + 1][0], s[2 * ks + 1][1]);
            pa[ks][3] = packh2(s[2 * ks + 1][2], s[2 * ks + 1][3]);
        }

        // ---- O += P V (V^T via ldmatrix.trans) ----
        #pragma unroll
        for (int ks = 0; ks < 4; ks++) {
            const int crow  = ks * 16 + (lane & 15);
            #pragma unroll
            for (int db = 0; db < 4; db++) {
                uint32_t vb[4];
                const int dbyte = db * 32 + ((lane >> 4) << 4);
                LDSM_X4_T(vb, vBase + SWZ128((uint32_t)(crow * 128 + dbyte)));
                MMA16816(o[db * 2],     pa[ks], vb[0], vb[1]);
                MMA16816(o[db * 2 + 1], pa[ks], vb[2], vb[3]);
            }
        }

        asm volatile("cp.async.wait_group 0;" ::: "memory");
        __syncthreads();
    }

    // ---- normalize + write ctx (fp16) ----
    const float inv1 = 1.0f / l1, inv2 = 1.0f / l2;
    #pragma unroll
    for (int t = 0; t < 8; t++) {
        const int col = t * 8 + cbase;
        *(__half2*)(Ctx + baseOff + (size_t)r1 * DMODEL + col) =
            __floats2half2_rn(o[t][0] * inv1, o[t][1] * inv1);
        *(__half2*)(Ctx + baseOff + (size_t)r2 * DMODEL + col) =
            __floats2half2_rn(o[t][2] * inv2, o[t][3] * inv2);
    }
}

// ============================================================
extern "C" void kernel_launch(void* const* d_in, const int* in_sizes, int n_in,
                              void* d_out, int out_size)
{
    const float* x  = (const float*)d_in[0];
    const float* Wq = (const float*)d_in[1];
    const float* Wk = (const float*)d_in[2];
    const float* Wv = (const float*)d_in[3];
    const float* Wo = (const float*)d_in[4];
    const float* bo = (const float*)d_in[5];
    float* out = (float*)d_out;

    __half *Qh, *Kh, *Vh, *Ch, *Xh, *Wqh, *Wkh, *Wvh, *Woh;
    cudaGetSymbolAddress((void**)&Qh, g_Qh);
    cudaGetSymbolAddress((void**)&Kh, g_Kh);
    cudaGetSymbolAddress((void**)&Vh, g_Vh);
    cudaGetSymbolAddress((void**)&Ch, g_Ctxh);
    cudaGetSymbolAddress((void**)&Xh, g_Xh);
    cudaGetSymbolAddress((void**)&Wqh, g_Wqh);
    cudaGetSymbolAddress((void**)&Wkh, g_Wkh);
    cudaGetSymbolAddress((void**)&Wvh, g_Wvh);
    cudaGetSymbolAddress((void**)&Woh, g_Woh);

    cudaFuncSetAttribute(hgemm_nt<__half>,
                         cudaFuncAttributeMaxDynamicSharedMemorySize, HG_SMEM);
    cudaFuncSetAttribute(hgemm_nt<float>,
                         cudaFuncAttributeMaxDynamicSharedMemorySize, HG_SMEM);
    cudaFuncSetAttribute(flash_hmma,
                         cudaFuncAttributeMaxDynamicSharedMemorySize, FL_SMEM);

    const int nX = MTOT * DMODEL, nW = DMODEL * DMODEL;
    f2h_kernel<<<nX / 4 / 256, 256>>>(x,  Xh,  nX);
    f2h_kernel<<<nW / 4 / 256, 256>>>(Wq, Wqh, nW);
    f2h_kernel<<<nW / 4 / 256, 256>>>(Wk, Wkh, nW);
    f2h_kernel<<<nW / 4 / 256, 256>>>(Wv, Wvh, nW);
    f2h_kernel<<<nW / 4 / 256, 256>>>(Wo, Woh, nW);

    dim3 gGemm(DMODEL / 128, MTOT / 128);   // (8, 32)
    hgemm_nt<__half><<<gGemm, 256, HG_SMEM>>>(Xh, Wqh, nullptr, Qh, MTOT, DMODEL, DMODEL);
    hgemm_nt<__half><<<gGemm, 256, HG_SMEM>>>(Xh, Wkh, nullptr, Kh, MTOT, DMODEL, DMODEL);
    hgemm_nt<__half><<<gGemm, 256, HG_SMEM>>>(Xh, Wvh, nullptr, Vh, MTOT, DMODEL, DMODEL);

    dim3 gFa(SEQ / 128, NHEADS, BATCH);     // (16, 16, 2)
    flash_hmma<<<gFa, 256, FL_SMEM>>>(Qh, Kh, Vh, Ch);

    hgemm_nt<float><<<gGemm, 256, HG_SMEM>>>(Ch, Woh, bo, out, MTOT, DMODEL, DMODEL);
}